// round 12
// baseline (speedup 1.0000x reference)
#include <cuda_runtime.h>
#include <math.h>

// WaveNet (reference batch/time mixup: output [64,1,64]; only x[:,:,0:84] used).
//
// R12 = R11 chain (2 pts/lane, tanh sigmoid, late-tap trees, residual folded
//       into the tanh FMA) with the two halo warps split into SEPARATE BLOCKS:
//   - grid 128 x 32: each warp stages its own weights, __syncwarp only
//     (no BAR.SYNC, no inter-warp skew wait)
//   - ownership is pairwise (warp0: l<16; warp1: 6<=l<22) -> one float2 store
//   - float2 x load in the prologue.

#define N_RES 20
#define FULL 0xFFFFFFFFu

__device__ __forceinline__ float tanha(float x) {
    float y; asm("tanh.approx.f32 %0, %1;" : "=f"(y) : "f"(x)); return y;
}

__global__ void __launch_bounds__(32, 1)
wavenet_halo_kernel(const float* __restrict__ x,
                    const float* __restrict__ w_in,
                    const float* __restrict__ b_in,
                    const float* __restrict__ wd,
                    const float* __restrict__ bd,
                    const float* __restrict__ wg,
                    const float* __restrict__ bg,
                    const float* __restrict__ w_out,
                    const float* __restrict__ b_out,
                    float* __restrict__ out)
{
    __shared__ __align__(16) float swd[N_RES * 8];   // 0.5 * dilated weights
    __shared__ __align__(16) float swg[N_RES * 8];   // 0.5 * gate weights
    __shared__ __align__(16) float sbd[N_RES * 2];   // 0.5 * dilated bias
    __shared__ __align__(16) float sbg[N_RES * 2];   // 0.5 * gate bias

    const int bid = blockIdx.x;
    const int b   = bid >> 1;          // batch
    const int w   = bid & 1;           // halo-warp role 0/1
    const int l   = threadIdx.x;       // lane

    // ---- stage half-scaled weights via float4 (this warp alone) ----
    {
        const float4* gwd = (const float4*)wd;   // 40 float4
        const float4* gwg = (const float4*)wg;   // 40 float4
#pragma unroll
        for (int k = l; k < 80; k += 32) {
            float4 v = (k < 40) ? gwd[k] : gwg[k - 40];
            v.x *= 0.5f; v.y *= 0.5f; v.z *= 0.5f; v.w *= 0.5f;
            if (k < 40) ((float4*)swd)[k]      = v;
            else        ((float4*)swg)[k - 40] = v;
        }
        if (l < 10) {
            float4 v = ((const float4*)bd)[l];
            v.x *= 0.5f; v.y *= 0.5f; v.z *= 0.5f; v.w *= 0.5f;
            ((float4*)sbd)[l] = v;
        } else if (l < 20) {
            float4 v = ((const float4*)bg)[l - 10];
            v.x *= 0.5f; v.y *= 0.5f; v.z *= 0.5f; v.w *= 0.5f;
            ((float4*)sbg)[l - 10] = v;
        }
    }

    const int base = w * 20;           // warp0 holds [0,64), warp1 holds [20,84)
    const int t0   = base + 2 * l;     // slot0 absolute time; slot1 = t0+1

    // pairwise output ownership: warp0 -> l<16 ([0,32)); warp1 -> 6<=l<22 ([32,64))
    const bool own  = w ? (l >= 6 && l < 22) : (l < 16);
    const bool pad0 = (w == 0 && l == 0);   // absolute t==0: d=2 left tap is pad

    // ---- conv_in: 1x1, C=1 -> F=2 (vector x load) ----
    const float2 xv = *(const float2*)(x + (size_t)b * 32768 + t0);
    const float wi0 = w_in[0], wi1 = w_in[1];
    const float bi0 = b_in[0], bi1 = b_in[1];
    float h0[2], h1[2];
    h0[0] = fmaf(wi0, xv.x, bi0);  h0[1] = fmaf(wi0, xv.y, bi0);
    h1[0] = fmaf(wi1, xv.x, bi1);  h1[1] = fmaf(wi1, xv.y, bi1);

    float s0[2] = {0.0f, 0.0f};
    float s1[2] = {0.0f, 0.0f};

    __syncwarp();                      // weights staged (warp-local)

    const float4* wd4 = (const float4*)swd;
    const float4* wg4 = (const float4*)swg;
    const float2* bd2 = (const float2*)sbd;
    const float2* bg2 = (const float2*)sbg;

#pragma unroll
    for (int i = 0; i < N_RES; i++) {
        const bool d1 = (i < 10);

        // right taps c = h[t+1]  (slot1's via shuffle -> chain-late)
        float c0s0 = h0[1], c1s0 = h1[1];
        float c0s1 = __shfl_down_sync(FULL, h0[0], 1);
        float c1s1 = __shfl_down_sync(FULL, h1[0], 1);

        // left taps: d=1 -> h[t]; d=2 -> h[t-1] (zero at absolute t=0)
        float a0s0, a1s0, a0s1, a1s1;
        if (d1) {
            a0s0 = h0[0]; a1s0 = h1[0];
            a0s1 = h0[1]; a1s1 = h1[1];
        } else {
            float u0 = __shfl_up_sync(FULL, h0[1], 1);
            float u1 = __shfl_up_sync(FULL, h1[1], 1);
            a0s0 = pad0 ? 0.0f : u0;
            a1s0 = pad0 ? 0.0f : u1;
            a0s1 = h0[0];
            a1s1 = h1[0];
        }

        const float4 wdv0 = wd4[2 * i], wdv1 = wd4[2 * i + 1];
        const float4 wgv0 = wg4[2 * i], wgv1 = wg4[2 * i + 1];
        const float2 bdv  = bd2[i];
        const float2 bgv  = bg2[i];

        // residual sources
        float r0s0 = d1 ? c0s0 : h0[0];
        float r1s0 = d1 ? c1s0 : h1[0];
        float r0s1 = d1 ? c0s1 : h0[1];
        float r1s1 = d1 ? c1s1 : h1[1];

        // ---- slot 0 ----  (a-taps early partial E, c-taps in last FMAs)
        {
            float Ed0 = fmaf(wdv0.x, a0s0, fmaf(wdv0.z, a1s0, bdv.x));
            float Ed1 = fmaf(wdv1.x, a0s0, fmaf(wdv1.z, a1s0, bdv.y));
            float Eg0 = fmaf(wgv0.x, a0s0, fmaf(wgv0.z, a1s0, bgv.x));
            float Eg1 = fmaf(wgv1.x, a0s0, fmaf(wgv1.z, a1s0, bgv.y));
            float cdh0 = fmaf(wdv0.y, c0s0, fmaf(wdv0.w, c1s0, Ed0));
            float cdh1 = fmaf(wdv1.y, c0s0, fmaf(wdv1.w, c1s0, Ed1));
            float ug0  = fmaf(wgv0.y, c0s0, fmaf(wgv0.w, c1s0, Eg0));
            float ug1  = fmaf(wgv1.y, c0s0, fmaf(wgv1.w, c1s0, Eg1));
            float th0 = tanha(ug0), th1 = tanha(ug1);
            h0[0] = fmaf(cdh0, th0, cdh0 + r0s0);   // pre in tanh's shadow
            h1[0] = fmaf(cdh1, th1, cdh1 + r1s0);
            s0[0] = fmaf(cdh0, th0, s0[0] + cdh0);  // off-chain
            s1[0] = fmaf(cdh1, th1, s1[0] + cdh1);
        }
        // ---- slot 1 ----
        {
            float Ed0 = fmaf(wdv0.x, a0s1, fmaf(wdv0.z, a1s1, bdv.x));
            float Ed1 = fmaf(wdv1.x, a0s1, fmaf(wdv1.z, a1s1, bdv.y));
            float Eg0 = fmaf(wgv0.x, a0s1, fmaf(wgv0.z, a1s1, bgv.x));
            float Eg1 = fmaf(wgv1.x, a0s1, fmaf(wgv1.z, a1s1, bgv.y));
            float cdh0 = fmaf(wdv0.y, c0s1, fmaf(wdv0.w, c1s1, Ed0));
            float cdh1 = fmaf(wdv1.y, c0s1, fmaf(wdv1.w, c1s1, Ed1));
            float ug0  = fmaf(wgv0.y, c0s1, fmaf(wgv0.w, c1s1, Eg0));
            float ug1  = fmaf(wgv1.y, c0s1, fmaf(wgv1.w, c1s1, Eg1));
            float th0 = tanha(ug0), th1 = tanha(ug1);
            h0[1] = fmaf(cdh0, th0, cdh0 + r0s1);
            h1[1] = fmaf(cdh1, th1, cdh1 + r1s1);
            s0[1] = fmaf(cdh0, th0, s0[1] + cdh0);
            s1[1] = fmaf(cdh1, th1, s1[1] + cdh1);
        }
    }

    // ---- conv_out over relu(per-point skip sum); one float2 store ----
    if (own) {
        const float wo0 = w_out[0], wo1 = w_out[1], bo = b_out[0];
        float2 o;
        o.x = fmaf(wo0, fmaxf(s0[0], 0.0f), fmaf(wo1, fmaxf(s1[0], 0.0f), bo));
        o.y = fmaf(wo0, fmaxf(s0[1], 0.0f), fmaf(wo1, fmaxf(s1[1], 0.0f), bo));
        *(float2*)(out + (size_t)b * 64 + t0) = o;
    }
}

extern "C" void kernel_launch(void* const* d_in, const int* in_sizes, int n_in,
                              void* d_out, int out_size)
{
    const float* x     = (const float*)d_in[0];
    const float* w_in  = (const float*)d_in[1];
    const float* b_in  = (const float*)d_in[2];
    const float* wd    = (const float*)d_in[3];
    const float* bd    = (const float*)d_in[4];
    const float* wg    = (const float*)d_in[5];
    const float* bg    = (const float*)d_in[6];
    const float* w_out = (const float*)d_in[7];
    const float* b_out = (const float*)d_in[8];
    float* out = (float*)d_out;

    wavenet_halo_kernel<<<128, 32>>>(x, w_in, b_in, wd, bd, wg, bg,
                                     w_out, b_out, out);
}

// round 13
// speedup vs baseline: 1.0338x; 1.0338x over previous
#include <cuda_runtime.h>
#include <math.h>

// WaveNet (reference batch/time mixup: output [64,1,64]; only x[:,:,0:84] used).
//
// R13 = R11 chain (grid 64 x block 64, 2 halo warps/batch, 2 pts/lane, tanh
//       sigmoid, late-tap trees, residual folded into the tanh FMA) with
//       SMEM staging REMOVED: weights are read straight into registers via
//       __ldg float4/float2 inside the fully-unrolled loop. ptxas front-
//       batches the loads (no 32-reg cap); the 0.5 prescale FMULs sit in the
//       LDG shadow. Kills LDG->FMUL->STS->sync->LDS prologue (~300 idle-clock
//       cycles ~ 0.6-0.9us at this kernel's parked clock).

#define N_RES 20
#define FULL 0xFFFFFFFFu

__device__ __forceinline__ float tanha(float x) {
    float y; asm("tanh.approx.f32 %0, %1;" : "=f"(y) : "f"(x)); return y;
}

__device__ __forceinline__ float4 half4(float4 v) {
    v.x *= 0.5f; v.y *= 0.5f; v.z *= 0.5f; v.w *= 0.5f; return v;
}

__global__ void __launch_bounds__(64, 1)
wavenet_halo_kernel(const float* __restrict__ x,
                    const float* __restrict__ w_in,
                    const float* __restrict__ b_in,
                    const float* __restrict__ wd,
                    const float* __restrict__ bd,
                    const float* __restrict__ wg,
                    const float* __restrict__ bg,
                    const float* __restrict__ w_out,
                    const float* __restrict__ b_out,
                    float* __restrict__ out)
{
    const int b   = blockIdx.x;
    const int tid = threadIdx.x;
    const int w   = tid >> 5;         // warp 0 / 1
    const int l   = tid & 31;

    const int base = w * 20;          // warp0 holds [0,64), warp1 holds [20,84)
    const int t0   = base + 2 * l;    // slot0 absolute time; slot1 = t0+1

    // pairwise output ownership: warp0 -> l<16 ([0,32)); warp1 -> 6<=l<22
    const bool own  = w ? (l >= 6 && l < 22) : (l < 16);
    const bool pad0 = (w == 0 && l == 0);   // absolute t==0: d=2 left tap pad

    const float4* gwd = (const float4*)wd;  // [layer][2] float4
    const float4* gwg = (const float4*)wg;
    const float2* gbd = (const float2*)bd;  // [layer] float2
    const float2* gbg = (const float2*)bg;

    // ---- conv_in: 1x1, C=1 -> F=2 (vector x load) ----
    const float2 xv = __ldg((const float2*)(x + (size_t)b * 32768 + t0));
    const float wi0 = __ldg(w_in), wi1 = __ldg(w_in + 1);
    const float bi0 = __ldg(b_in), bi1 = __ldg(b_in + 1);
    float h0[2], h1[2];
    h0[0] = fmaf(wi0, xv.x, bi0);  h0[1] = fmaf(wi0, xv.y, bi0);
    h1[0] = fmaf(wi1, xv.x, bi1);  h1[1] = fmaf(wi1, xv.y, bi1);

    float s0[2] = {0.0f, 0.0f};
    float s1[2] = {0.0f, 0.0f};

#pragma unroll
    for (int i = 0; i < N_RES; i++) {
        const bool d1 = (i < 10);

        // weights straight from L2, prescaled by 0.5 in the LDG shadow
        const float4 wdv0 = half4(__ldg(gwd + 2 * i));
        const float4 wdv1 = half4(__ldg(gwd + 2 * i + 1));
        const float4 wgv0 = half4(__ldg(gwg + 2 * i));
        const float4 wgv1 = half4(__ldg(gwg + 2 * i + 1));
        float2 bdv = __ldg(gbd + i);  bdv.x *= 0.5f; bdv.y *= 0.5f;
        float2 bgv = __ldg(gbg + i);  bgv.x *= 0.5f; bgv.y *= 0.5f;

        // right taps c = h[t+1]  (slot1's via shuffle -> chain-late)
        float c0s0 = h0[1], c1s0 = h1[1];
        float c0s1 = __shfl_down_sync(FULL, h0[0], 1);
        float c1s1 = __shfl_down_sync(FULL, h1[0], 1);

        // left taps: d=1 -> h[t]; d=2 -> h[t-1] (zero at absolute t=0)
        float a0s0, a1s0, a0s1, a1s1;
        if (d1) {
            a0s0 = h0[0]; a1s0 = h1[0];
            a0s1 = h0[1]; a1s1 = h1[1];
        } else {
            float u0 = __shfl_up_sync(FULL, h0[1], 1);
            float u1 = __shfl_up_sync(FULL, h1[1], 1);
            a0s0 = pad0 ? 0.0f : u0;
            a1s0 = pad0 ? 0.0f : u1;
            a0s1 = h0[0];
            a1s1 = h1[0];
        }

        // residual sources
        float r0s0 = d1 ? c0s0 : h0[0];
        float r1s0 = d1 ? c1s0 : h1[0];
        float r0s1 = d1 ? c0s1 : h0[1];
        float r1s1 = d1 ? c1s1 : h1[1];

        // ---- slot 0 ----  (a-taps early partial E, c-taps in last FMAs)
        {
            float Ed0 = fmaf(wdv0.x, a0s0, fmaf(wdv0.z, a1s0, bdv.x));
            float Ed1 = fmaf(wdv1.x, a0s0, fmaf(wdv1.z, a1s0, bdv.y));
            float Eg0 = fmaf(wgv0.x, a0s0, fmaf(wgv0.z, a1s0, bgv.x));
            float Eg1 = fmaf(wgv1.x, a0s0, fmaf(wgv1.z, a1s0, bgv.y));
            float cdh0 = fmaf(wdv0.y, c0s0, fmaf(wdv0.w, c1s0, Ed0));
            float cdh1 = fmaf(wdv1.y, c0s0, fmaf(wdv1.w, c1s0, Ed1));
            float ug0  = fmaf(wgv0.y, c0s0, fmaf(wgv0.w, c1s0, Eg0));
            float ug1  = fmaf(wgv1.y, c0s0, fmaf(wgv1.w, c1s0, Eg1));
            float th0 = tanha(ug0), th1 = tanha(ug1);
            h0[0] = fmaf(cdh0, th0, cdh0 + r0s0);   // pre in tanh's shadow
            h1[0] = fmaf(cdh1, th1, cdh1 + r1s0);
            s0[0] = fmaf(cdh0, th0, s0[0] + cdh0);  // off-chain
            s1[0] = fmaf(cdh1, th1, s1[0] + cdh1);
        }
        // ---- slot 1 ----
        {
            float Ed0 = fmaf(wdv0.x, a0s1, fmaf(wdv0.z, a1s1, bdv.x));
            float Ed1 = fmaf(wdv1.x, a0s1, fmaf(wdv1.z, a1s1, bdv.y));
            float Eg0 = fmaf(wgv0.x, a0s1, fmaf(wgv0.z, a1s1, bgv.x));
            float Eg1 = fmaf(wgv1.x, a0s1, fmaf(wgv1.z, a1s1, bgv.y));
            float cdh0 = fmaf(wdv0.y, c0s1, fmaf(wdv0.w, c1s1, Ed0));
            float cdh1 = fmaf(wdv1.y, c0s1, fmaf(wdv1.w, c1s1, Ed1));
            float ug0  = fmaf(wgv0.y, c0s1, fmaf(wgv0.w, c1s1, Eg0));
            float ug1  = fmaf(wgv1.y, c0s1, fmaf(wgv1.w, c1s1, Eg1));
            float th0 = tanha(ug0), th1 = tanha(ug1);
            h0[1] = fmaf(cdh0, th0, cdh0 + r0s1);
            h1[1] = fmaf(cdh1, th1, cdh1 + r1s1);
            s0[1] = fmaf(cdh0, th0, s0[1] + cdh0);
            s1[1] = fmaf(cdh1, th1, s1[1] + cdh1);
        }
    }

    // ---- conv_out over relu(per-point skip sum); one float2 store ----
    if (own) {
        const float wo0 = __ldg(w_out), wo1 = __ldg(w_out + 1);
        const float bo  = __ldg(b_out);
        float2 o;
        o.x = fmaf(wo0, fmaxf(s0[0], 0.0f), fmaf(wo1, fmaxf(s1[0], 0.0f), bo));
        o.y = fmaf(wo0, fmaxf(s0[1], 0.0f), fmaf(wo1, fmaxf(s1[1], 0.0f), bo));
        *(float2*)(out + (size_t)b * 64 + t0) = o;
    }
}

extern "C" void kernel_launch(void* const* d_in, const int* in_sizes, int n_in,
                              void* d_out, int out_size)
{
    const float* x     = (const float*)d_in[0];
    const float* w_in  = (const float*)d_in[1];
    const float* b_in  = (const float*)d_in[2];
    const float* wd    = (const float*)d_in[3];
    const float* bd    = (const float*)d_in[4];
    const float* wg    = (const float*)d_in[5];
    const float* bg    = (const float*)d_in[6];
    const float* w_out = (const float*)d_in[7];
    const float* b_out = (const float*)d_in[8];
    float* out = (float*)d_out;

    wavenet_halo_kernel<<<64, 64>>>(x, w_in, b_in, wd, bd, wg, bg,
                                    w_out, b_out, out);
}